// round 17
// baseline (speedup 1.0000x reference)
#include <cuda_runtime.h>
#include <math.h>
#include <float.h>

// UCBSampler: rewards[i,j] = probs[i,j] + 0.5*sqrt(log(i+1) / (1 + i*(1 + i*N + j)))
// out[i] = (float)argmax_j rewards[i,j]  (first index on ties).
//
// Round-17: warp-autonomous half-row kernel. R16 (register-resident quarters,
// 100.0us) lost ~35% DRAM duty to per-CTA reduction tails. Fixes:
//  - threshold uses the WARP's own max Mw (<= row max) -> looser but provably
//    safe filter; kills the first block reduce + both its __syncthreads
//  - half-row CTAs (512 thr, 8 float4/thread): half as many tails/atomics
//  - single __syncthreads before the final 16-way merge + atomic combine
// Exact reference-rounded math, min-index ties, packed-u64 atomicMax combine
// all unchanged (verified R11-R16).

#define NNODES  32000
#define HELEMS  16000             // elements per half
#define HV4     (HELEMS / 4)      // 4000 float4
#define BATCH   4096
#define THREADS 512
#define VPT     8                 // float4 per thread (4096 slots >= 4000)
#define NWARP   (THREADS / 32)

__device__ unsigned long long g_key[BATCH];   // packed (reward, ~index)
__device__ unsigned int       g_cnt[BATCH];   // arrival counters (mod 2)

__global__ __launch_bounds__(THREADS)
void ucb_half_kernel(const float* __restrict__ probs,
                     float* __restrict__ out)
{
    __shared__ float s_v[NWARP];
    __shared__ int   s_i[NWARP];

    const int cta = blockIdx.x;
    const int row = cta >> 1;
    const int h   = cta & 1;
    const int t   = threadIdx.x;
    const int j0  = h * HELEMS;

    const float4* gp = reinterpret_cast<const float4*>(
        probs + (size_t)row * NNODES + j0);

    // ---- Phase 1: load 8 float4 into registers, running max ----
    float4 r[VPT];
    float lmax = -FLT_MAX;
    #pragma unroll
    for (int v = 0; v < VPT; v++) {
        int f = t + v * THREADS;
        if (f < HV4) {
            r[v] = gp[f];
        } else {
            r[v] = make_float4(-1.0f, -1.0f, -1.0f, -1.0f);  // below thresh
        }
        lmax = fmaxf(lmax,
               fmaxf(fmaxf(r[v].x, r[v].y), fmaxf(r[v].z, r[v].w)));
    }

    // ---- warp max reduce -> Mw (no __syncthreads needed) ----
    float Mw = lmax;
    #pragma unroll
    for (int o = 16; o > 0; o >>= 1)
        Mw = fmaxf(Mw, __shfl_xor_sync(0xffffffffu, Mw, o));

    // ---- per-row constants (reference f32 association) ----
    const float fi = (float)row;
    const float L  = logf(fi + 1.0f);                    // log(1)=0 exact
    const float base_inner = __fadd_rn(1.0f, __fmul_rn(fi, (float)NNODES));

    // spread bound over THIS half's j-range (inflated; not bit-critical).
    // thresh uses warp max Mw <= row max M1 -> looser than M1-spread,
    // therefore still provably includes every possible winner in this warp.
    const float dA = __fadd_rn(1.0f,
                      __fmul_rn(fi, __fadd_rn(base_inner, (float)j0)));
    const float dB = __fadd_rn(1.0f,
                      __fmul_rn(fi, __fadd_rn(base_inner, (float)(j0 + HELEMS - 1))));
    const float bA = 0.5f * sqrtf(L / dA);
    const float bB = 0.5f * sqrtf(L / dB);
    const float thresh = Mw - (bA - bB) * 1.01f - 1e-6f;

    // ---- Phase 2: register rescan vs fixed warp threshold ----
    float bestv = -FLT_MAX;
    int   besti = 0x7fffffff;
    #pragma unroll
    for (int v = 0; v < VPT; v++) {
        float m4 = fmaxf(fmaxf(r[v].x, r[v].y), fmaxf(r[v].z, r[v].w));
        if (m4 >= thresh) {                              // rare
            float pv[4] = {r[v].x, r[v].y, r[v].z, r[v].w};
            #pragma unroll
            for (int k = 0; k < 4; k++) {
                if (pv[k] >= thresh) {
                    int   j     = j0 + 4 * (t + v * THREADS) + k;
                    // exact reference rounding (verified R9/R11-R16)
                    float inner = __fadd_rn(base_inner, (float)j);
                    float denom = __fadd_rn(1.0f, __fmul_rn(fi, inner));
                    float b = __fmul_rn(0.5f, __fsqrt_rn(__fdiv_rn(L, denom)));
                    float rr = __fadd_rn(pv[k], b);
                    if (rr > bestv || (rr == bestv && j < besti)) {
                        bestv = rr; besti = j;
                    }
                }
            }
        }
    }

    // ---- warp (val, idx) argmax reduce, tie -> min idx ----
    #pragma unroll
    for (int o = 16; o > 0; o >>= 1) {
        float ov = __shfl_xor_sync(0xffffffffu, bestv, o);
        int   oi = __shfl_xor_sync(0xffffffffu, besti, o);
        if (ov > bestv || (ov == bestv && oi < besti)) { bestv = ov; besti = oi; }
    }
    if ((t & 31) == 0) { s_v[t >> 5] = bestv; s_i[t >> 5] = besti; }
    __syncthreads();                       // the ONLY block-wide sync

    if (t == 0) {
        float v2 = s_v[0]; int i2 = s_i[0];
        #pragma unroll
        for (int w = 1; w < NWARP; w++) {
            float ov = s_v[w]; int oi = s_i[w];
            if (ov > v2 || (ov == v2 && oi < i2)) { v2 = ov; i2 = oi; }
        }
        // ---- packed-key atomic combine + last-arrival output write ----
        // rewards > 0 => float bits order-preserving as unsigned.
        unsigned long long key =
            ((unsigned long long)__float_as_uint(v2) << 32)
            | (unsigned)(0x7FFFFFFFu - (unsigned)i2);    // tie -> smaller j
        atomicMax(&g_key[row], key);
        __threadfence();
        unsigned int old = atomicAdd(&g_cnt[row], 1u);
        if ((old & 1u) == 1u) {                          // 2nd half arrival
            unsigned long long k =
                *(volatile unsigned long long*)&g_key[row];
            out[row] = (float)(int)(0x7FFFFFFFu - (unsigned)(k & 0xFFFFFFFFu));
        }
    }
}

extern "C" void kernel_launch(void* const* d_in, const int* in_sizes, int n_in,
                              void* d_out, int out_size)
{
    const float* probs = (const float*)d_in[0];
    float*       out   = (float*)d_out;
    (void)in_sizes; (void)n_in; (void)out_size;

    ucb_half_kernel<<<BATCH * 2, THREADS>>>(probs, out);
}